// round 5
// baseline (speedup 1.0000x reference)
#include <cuda_runtime.h>

// Scratch: transposed weight [G][L] = [8][4096] floats (128 KB)
__device__ float g_wt[8 * 4096];

__global__ void transpose_w_kernel(const float* __restrict__ w) {
    int idx = blockIdx.x * blockDim.x + threadIdx.x;
    if (idx < 8 * 4096) {
        int g = idx >> 12;        // / 4096
        int l = idx & 4095;       // % 4096
        g_wt[idx] = w[l * 8 + g]; // w is [L, G]
    }
}

// 128B vector load with L2 256B fetch-granularity hint (read-only path).
// Non-volatile, no memory clobber: scheduler keeps full reorder freedom.
__device__ __forceinline__ float4 ldg_x(const float4* p) {
    float4 v;
    asm("ld.global.nc.L2::256B.v4.f32 {%0,%1,%2,%3}, [%4];"
        : "=f"(v.x), "=f"(v.y), "=f"(v.z), "=f"(v.w)
        : "l"(p));
    return v;
}

// One warp per (b, g) output element (R0 skeleton: 29 regs, ~90% occ).
__global__ __launch_bounds__(256) void grouped_fc_kernel(
    const float* __restrict__ x,
    const float* __restrict__ bias,
    float* __restrict__ out)
{
    const int warp_global = (blockIdx.x * blockDim.x + threadIdx.x) >> 5; // 0..65535
    const int lane = threadIdx.x & 31;
    const int g = warp_global & 7;

    const float4* __restrict__ xp =
        reinterpret_cast<const float4*>(x + (size_t)warp_global * 4096) + lane;
    const float4* __restrict__ wp =
        reinterpret_cast<const float4*>(g_wt + g * 4096) + lane;

    float a0 = 0.f, a1 = 0.f, a2 = 0.f, a3 = 0.f;

    // 4096 elems / (32 lanes * 4 per float4) = 32 iterations.
    #pragma unroll 8
    for (int i = 0; i < 32; i++) {
        float4 xv = ldg_x(xp + i * 32);
        float4 wv = wp[i * 32];
        a0 = fmaf(xv.x, wv.x, a0);
        a1 = fmaf(xv.y, wv.y, a1);
        a2 = fmaf(xv.z, wv.z, a2);
        a3 = fmaf(xv.w, wv.w, a3);
    }

    float s = (a0 + a1) + (a2 + a3);
    #pragma unroll
    for (int off = 16; off > 0; off >>= 1)
        s += __shfl_xor_sync(0xFFFFFFFFu, s, off);

    if (lane == 0)
        out[warp_global] = s + __ldg(&bias[g]);
}

extern "C" void kernel_launch(void* const* d_in, const int* in_sizes, int n_in,
                              void* d_out, int out_size) {
    const float* x      = (const float*)d_in[0]; // [8192, 8, 4096]
    const float* weight = (const float*)d_in[1]; // [1, 4096, 8]
    const float* bias   = (const float*)d_in[2]; // [8]
    float* out          = (float*)d_out;         // [8192, 8]

    transpose_w_kernel<<<(8 * 4096 + 255) / 256, 256>>>(weight);

    // 8192 blocks x 256 threads = 65536 warps, one per output element.
    grouped_fc_kernel<<<8192, 256>>>(x, bias, out);
}

// round 6
// speedup vs baseline: 1.1269x; 1.1269x over previous
#include <cuda_runtime.h>

// Scratch: transposed weight [G][L] = [8][4096] floats (128 KB)
__device__ float g_wt[8 * 4096];

__global__ void transpose_w_kernel(const float* __restrict__ w) {
    int idx = blockIdx.x * blockDim.x + threadIdx.x;
    if (idx < 8 * 4096) {
        int g = idx >> 12;        // / 4096
        int l = idx & 4095;       // % 4096
        g_wt[idx] = w[l * 8 + g]; // w is [L, G]
    }
}

// Block layout: g = bid & 7; warps 0..7 handle b = (bid>>3)*8 + warp.
// One 16KB weight row (for g) is staged in smem once per block, so the
// inner loop does 32 x-LDG.128 + 32 LDS.128 (weight off the L1tex path).
__global__ __launch_bounds__(256) void grouped_fc_kernel(
    const float* __restrict__ x,
    const float* __restrict__ bias,
    float* __restrict__ out)
{
    __shared__ float4 w_sh[1024];  // 4096 floats = 16 KB

    const int g      = blockIdx.x & 7;
    const int b_base = (blockIdx.x >> 3) << 3;

    // Cooperative coalesced fill from L2-resident transposed weight.
    const float4* __restrict__ wsrc =
        reinterpret_cast<const float4*>(g_wt + (g << 12));
    #pragma unroll
    for (int i = 0; i < 4; i++)
        w_sh[threadIdx.x + i * 256] = wsrc[threadIdx.x + i * 256];
    __syncthreads();

    const int warp = threadIdx.x >> 5;  // 0..7
    const int lane = threadIdx.x & 31;
    const int row  = (b_base + warp) * 8 + g;

    const float4* __restrict__ xp =
        reinterpret_cast<const float4*>(x + (size_t)row * 4096) + lane;

    float a0 = 0.f, a1 = 0.f, a2 = 0.f, a3 = 0.f;

    // 4096 elems / (32 lanes * 4 per float4) = 32 iterations.
    #pragma unroll 8
    for (int i = 0; i < 32; i++) {
        float4 xv = xp[i * 32];
        float4 wv = w_sh[lane + i * 32];   // conflict-free LDS.128
        a0 = fmaf(xv.x, wv.x, a0);
        a1 = fmaf(xv.y, wv.y, a1);
        a2 = fmaf(xv.z, wv.z, a2);
        a3 = fmaf(xv.w, wv.w, a3);
    }

    float s = (a0 + a1) + (a2 + a3);
    #pragma unroll
    for (int off = 16; off > 0; off >>= 1)
        s += __shfl_xor_sync(0xFFFFFFFFu, s, off);

    if (lane == 0)
        out[row] = s + __ldg(&bias[g]);
}

extern "C" void kernel_launch(void* const* d_in, const int* in_sizes, int n_in,
                              void* d_out, int out_size) {
    const float* x      = (const float*)d_in[0]; // [8192, 8, 4096]
    const float* weight = (const float*)d_in[1]; // [1, 4096, 8]
    const float* bias   = (const float*)d_in[2]; // [8]
    float* out          = (float*)d_out;         // [8192, 8]

    transpose_w_kernel<<<(8 * 4096 + 255) / 256, 256>>>(weight);

    // 8192 blocks: 1024 b-tiles x 8 groups; 8 warps per block.
    grouped_fc_kernel<<<8192, 256>>>(x, bias, out);
}